// round 2
// baseline (speedup 1.0000x reference)
#include <cuda_runtime.h>
#include <cuda_bf16.h>
#include <math.h>
#include <stdint.h>

// ---------------- problem constants (fixed by setup_inputs) ----------------
#define BATCH     32
#define TT        64
#define NCONT     2048          // B*T
#define CCH       64
#define HH        160
#define WW        160
#define PPTS      32            // NUM_POINTS / STRIDE
#define KCONV     2112          // 66 * 32
#define NEMBD     512
#define QKDIM     1024
#define HEADS     8

// ---------------- scratch (__device__ globals; no runtime alloc) -----------
__device__ float g_cf_in[NCONT * KCONV];   // A matrix for conv GEMM (n, c*32+p)
__device__ float g_cf   [NCONT * NEMBD];   // conv output
__device__ float g_qk   [NCONT * QKDIM];   // q|k
__device__ int   g_mask [NCONT];
__device__ int   g_order[NCONT];

// ---------------- K1: bilinear gather + build conv-GEMM input --------------
__global__ __launch_bounds__(256) void gather_kernel(
    const float* __restrict__ cnn,       // (32,64,160,160)
    const float* __restrict__ contours,  // (2048,128,2)
    const int*   __restrict__ img_idx)   // (2048,)
{
    int n   = blockIdx.x;
    int tid = threadIdx.x;

    __shared__ int   s_off[4][PPTS];
    __shared__ float s_wt [4][PPTS];
    __shared__ float s_x[PPTS], s_y[PPTS];
    __shared__ int   s_b;

    if (tid == 0) s_b = img_idx[n];
    if (tid < PPTS) {
        int p = tid;
        float x = contours[((size_t)n * 128 + p * 4) * 2 + 0];
        float y = contours[((size_t)n * 128 + p * 4) * 2 + 1];
        s_x[p] = x; s_y[p] = y;
        float px = x * 0.25f - 0.5f;     // * (W/w) = 160/640
        float py = y * 0.25f - 0.5f;
        float x0 = floorf(px), y0 = floorf(py);
        float fx = px - x0, fy = py - y0;
        float xs[2] = { x0, x0 + 1.f };
        float ys[2] = { y0, y0 + 1.f };
        float wx[2] = { 1.f - fx, fx };
        float wy[2] = { 1.f - fy, fy };
#pragma unroll
        for (int t = 0; t < 4; t++) {
            float xi = xs[t & 1], yi = ys[t >> 1];
            bool valid = (xi >= 0.f) && (xi < 160.f) && (yi >= 0.f) && (yi < 160.f);
            int xc = (int)fminf(fmaxf(xi, 0.f), 159.f);
            int yc = (int)fminf(fmaxf(yi, 0.f), 159.f);
            s_off[t][p] = yc * WW + xc;
            s_wt [t][p] = valid ? wx[t & 1] * wy[t >> 1] : 0.f;
        }
    }
    __syncthreads();

    int b = s_b;
    float* out = g_cf_in + (size_t)n * KCONV;
    for (int k = tid; k < KCONV; k += 256) {
        int c = k >> 5, p = k & 31;
        float v;
        if (c < CCH) {
            const float* base = cnn + (size_t)(b * CCH + c) * (HH * WW);
            v = s_wt[0][p] * __ldg(base + s_off[0][p])
              + s_wt[1][p] * __ldg(base + s_off[1][p])
              + s_wt[2][p] * __ldg(base + s_off[2][p])
              + s_wt[3][p] * __ldg(base + s_off[3][p]);
        } else if (c == CCH) {
            v = s_x[p] * (1.0f / 640.f);
        } else {
            v = s_y[p] * (1.0f / 640.f);
        }
        out[k] = v;
    }
}

// ---------------- K2: mask dtype probe + prefix-sum order ------------------
__global__ __launch_bounds__(1024) void scan_order_kernel(
    const void* __restrict__ ct01)
{
    __shared__ int sA[NCONT], sB[NCONT];
    __shared__ int flags[2];            // [0]=not int32-like, [1]=not f32-like
    int tid = threadIdx.x;
    if (tid < 2) flags[tid] = 0;
    __syncthreads();
    // probe first 2048 bytes (in-bounds for every candidate dtype)
    if (tid < 512) {
        int v = ((const int*)ct01)[tid];
        if (v != 0 && v != 1) flags[0] = 1;
        float f = __int_as_float(v);
        if (!(f == 0.0f || f == 1.0f)) flags[1] = 1;
    }
    __syncthreads();
    int dtype = (flags[0] == 0) ? 0 : ((flags[1] == 0) ? 1 : 2); // 0=i32,1=f32,2=u8

    for (int i = tid; i < NCONT; i += 1024) {
        int m;
        if (dtype == 0)      m = ((const int*)ct01)[i] != 0;
        else if (dtype == 1) m = ((const float*)ct01)[i] != 0.0f;
        else                 m = ((const unsigned char*)ct01)[i] != 0;
        sA[i] = m;
        g_mask[i] = m;
    }
    __syncthreads();

    int* src = sA; int* dst = sB;
    for (int off = 1; off < NCONT; off <<= 1) {
        for (int i = tid; i < NCONT; i += 1024) {
            int v = src[i];
            if (i >= off) v += src[i - off];
            dst[i] = v;
        }
        __syncthreads();
        int* t = src; src = dst; dst = t;
    }
    for (int i = tid; i < NCONT; i += 1024) {
        int o = src[i] - 1;
        o = min(max(o, 0), NCONT - 1);
        g_order[i] = o;
    }
}

// ---------------- K3/K4: tiled NT SGEMM: C = A(MxK) * B(NxK)^T + epi -------
// POS_EPI=1 : A = g_cf_in, C = g_cf,  bias+pos epilogue
// POS_EPI=0 : A = g_cf,    C = g_qk,  bias epilogue
template <bool POS_EPI>
__global__ __launch_bounds__(256) void gemm_nt_kernel(
    const float* __restrict__ B,
    const float* __restrict__ bias, const float* __restrict__ pos,
    const int* __restrict__ ct_ind, int N, int K)
{
    const int BM = 64, BN = 64, BK = 16;
    __shared__ float As[BK][BM + 4];
    __shared__ float Bs[BK][BN + 4];

    const float* A = POS_EPI ? g_cf_in : g_cf;
    float*       C = POS_EPI ? g_cf    : g_qk;

    int tid = threadIdx.x;
    int m0 = blockIdx.y * BM;
    int n0 = blockIdx.x * BN;

    int lr = tid >> 2;          // 0..63: row within tile
    int lk = (tid & 3) * 4;     // 0,4,8,12: k quad
    int ty = tid >> 4;          // 0..15
    int tx = tid & 15;          // 0..15

    float acc[4][4] = {};

    for (int k0 = 0; k0 < K; k0 += BK) {
        float4 av = *(const float4*)&A[(size_t)(m0 + lr) * K + k0 + lk];
        float4 bv = *(const float4*)&B[(size_t)(n0 + lr) * K + k0 + lk];
        As[lk + 0][lr] = av.x; As[lk + 1][lr] = av.y;
        As[lk + 2][lr] = av.z; As[lk + 3][lr] = av.w;
        Bs[lk + 0][lr] = bv.x; Bs[lk + 1][lr] = bv.y;
        Bs[lk + 2][lr] = bv.z; Bs[lk + 3][lr] = bv.w;
        __syncthreads();
#pragma unroll
        for (int k = 0; k < BK; k++) {
            float4 a = *(const float4*)&As[k][ty * 4];
            float4 b = *(const float4*)&Bs[k][tx * 4];
            acc[0][0] += a.x * b.x; acc[0][1] += a.x * b.y;
            acc[0][2] += a.x * b.z; acc[0][3] += a.x * b.w;
            acc[1][0] += a.y * b.x; acc[1][1] += a.y * b.y;
            acc[1][2] += a.y * b.z; acc[1][3] += a.y * b.w;
            acc[2][0] += a.z * b.x; acc[2][1] += a.z * b.y;
            acc[2][2] += a.z * b.z; acc[2][3] += a.z * b.w;
            acc[3][0] += a.w * b.x; acc[3][1] += a.w * b.y;
            acc[3][2] += a.w * b.z; acc[3][3] += a.w * b.w;
        }
        __syncthreads();
    }

#pragma unroll
    for (int i = 0; i < 4; i++) {
        int m = m0 + ty * 4 + i;
        int pbase = 0;
        if (POS_EPI) {
            int idx = ct_ind[m];
            int cx = (idx % WW) / 10;       // ((idx%160)*16)//160
            int cy = (idx / WW) / 10;       // ((idx//160)*16)//160
            pbase = cy * 16 + cx;
        }
#pragma unroll
        for (int j = 0; j < 4; j++) {
            int nn = n0 + tx * 4 + j;
            float v = acc[i][j] + bias[nn];
            if (POS_EPI) v += pos[(size_t)nn * 256 + pbase];
            C[(size_t)m * N + nn] = v;
        }
    }
}

// ---------------- K5: per-image attention + head combine + sigmoid ---------
__global__ __launch_bounds__(256) void attn_kernel(
    const float* __restrict__ p_w, float* __restrict__ out)
{
    int b = blockIdx.x;
    int tid = threadIdx.x;

    __shared__ float Qs[32][TT + 4];
    __shared__ float Ks[32][TT + 4];
    __shared__ float pw[HEADS];
    __shared__ int s_ord[TT], s_msk[TT];

    if (tid < HEADS) pw[tid] = p_w[tid];
    if (tid < TT) {
        int i = b * TT + tid;
        s_ord[tid] = g_order[i];
        s_msk[tid] = g_mask[i];
    }
    __syncthreads();

    int ty = tid >> 4, tx = tid & 15;
    float acc[4][4] = {};

    for (int d0 = 0; d0 < NEMBD; d0 += 32) {
#pragma unroll
        for (int l = 0; l < 8; l++) {
            int e = tid + l * 256;     // 0..2047
            int t = e >> 5, dd = e & 31;
            int d = d0 + dd;
            float qv = 0.f, kv = 0.f;
            if (s_msk[t]) {
                const float* row = g_qk + (size_t)s_ord[t] * QKDIM;
                qv = row[d] * pw[d >> 6];
                kv = row[NEMBD + d];
            }
            Qs[dd][t] = qv;
            Ks[dd][t] = kv;
        }
        __syncthreads();
#pragma unroll
        for (int dd = 0; dd < 32; dd++) {
            float4 a = *(const float4*)&Qs[dd][ty * 4];
            float4 c = *(const float4*)&Ks[dd][tx * 4];
            acc[0][0] += a.x * c.x; acc[0][1] += a.x * c.y;
            acc[0][2] += a.x * c.z; acc[0][3] += a.x * c.w;
            acc[1][0] += a.y * c.x; acc[1][1] += a.y * c.y;
            acc[1][2] += a.y * c.z; acc[1][3] += a.y * c.w;
            acc[2][0] += a.z * c.x; acc[2][1] += a.z * c.y;
            acc[2][2] += a.z * c.z; acc[2][3] += a.z * c.w;
            acc[3][0] += a.w * c.x; acc[3][1] += a.w * c.y;
            acc[3][2] += a.w * c.z; acc[3][3] += a.w * c.w;
        }
        __syncthreads();
    }

#pragma unroll
    for (int i = 0; i < 4; i++) {
        int t = ty * 4 + i;
#pragma unroll
        for (int j = 0; j < 4; j++) {
            int s = tx * 4 + j;
            float v = acc[i][j] * 0.125f;         // 1/sqrt(64)
            float sg = 1.f / (1.f + expf(-v));
            if (isnan(sg)) sg = 0.f;
            out[(size_t)b * (TT * TT) + t * TT + s] = sg;
        }
    }
}

// ---------------- launch ----------------------------------------------------
extern "C" void kernel_launch(void* const* d_in, const int* in_sizes, int n_in,
                              void* d_out, int out_size)
{
    const float* cnn      = (const float*)d_in[0];
    const float* contours = (const float*)d_in[1];
    const void*  ct01     = (const void*) d_in[2];
    const int*   img_idx  = (const int*)  d_in[3];
    const int*   ct_ind   = (const int*)  d_in[4];
    // d_in[5]=h, d_in[6]=w : fixed at 640, hardcoded
    const float* conv_w   = (const float*)d_in[7];   // (512, 66, 32) -> (512, 2112)
    const float* conv_b   = (const float*)d_in[8];
    const float* attn_w   = (const float*)d_in[9];   // (1024, 512)
    const float* attn_b   = (const float*)d_in[10];
    const float* p_w      = (const float*)d_in[11];  // 8 floats
    const float* pos      = (const float*)d_in[12];  // (512, 16, 16)
    float* out = (float*)d_out;

    scan_order_kernel<<<1, 1024>>>(ct01);
    gather_kernel<<<NCONT, 256>>>(cnn, contours, img_idx);

    {
        dim3 grid(NEMBD / 64, NCONT / 64);
        gemm_nt_kernel<true><<<grid, 256>>>(conv_w, conv_b, pos, ct_ind,
                                            NEMBD, KCONV);
    }
    {
        dim3 grid(QKDIM / 64, NCONT / 64);
        gemm_nt_kernel<false><<<grid, 256>>>(attn_w, attn_b, nullptr, nullptr,
                                             QKDIM, NEMBD);
    }
    attn_kernel<<<BATCH, 256>>>(p_w, out);
}